// round 1
// baseline (speedup 1.0000x reference)
#include <cuda_runtime.h>

// region layer: x (16, 425, 76, 76) f32 -> out (16, 415, 76, 76) f32
// per anchor (5 anchors x 85 ch): sigmoid(ch0,1), drop ch2,3, sigmoid(ch4),
// softmax over ch5..84 -> 83 output channels per anchor.

#define BATCH   16
#define NANCH   5
#define NCLS    80
#define CIN     425   // NANCH * 85
#define COUT    415   // NANCH * 83
#define HW      (76 * 76)   // 5776

__global__ __launch_bounds__(256) void region_kernel(
    const float* __restrict__ x, float* __restrict__ out)
{
    const int tid = blockIdx.x * blockDim.x + threadIdx.x;
    const int total = BATCH * NANCH * HW;
    if (tid >= total) return;

    const int hw = tid % HW;
    const int t  = tid / HW;
    const int a  = t % NANCH;
    const int b  = t / NANCH;

    const float* __restrict__ in = x   + ((size_t)(b * CIN  + a * 85) * HW) + hw;
    float*       __restrict__ o  = out + ((size_t)(b * COUT + a * 83) * HW) + hw;

    // sigmoid channels
    const float v0 = in[(size_t)0 * HW];
    const float v1 = in[(size_t)1 * HW];
    const float v4 = in[(size_t)4 * HW];

    // class logits -> registers (coalesced strided loads)
    float c[NCLS];
    #pragma unroll
    for (int j = 0; j < NCLS; j++)
        c[j] = in[(size_t)(5 + j) * HW];

    // softmax over the 80 classes
    float m = c[0];
    #pragma unroll
    for (int j = 1; j < NCLS; j++)
        m = fmaxf(m, c[j]);

    float s = 0.0f;
    #pragma unroll
    for (int j = 0; j < NCLS; j++) {
        c[j] = __expf(c[j] - m);
        s += c[j];
    }
    const float inv = __frcp_rn(s);

    o[(size_t)0 * HW] = 1.0f / (1.0f + __expf(-v0));
    o[(size_t)1 * HW] = 1.0f / (1.0f + __expf(-v1));
    o[(size_t)2 * HW] = 1.0f / (1.0f + __expf(-v4));

    #pragma unroll
    for (int j = 0; j < NCLS; j++)
        o[(size_t)(3 + j) * HW] = c[j] * inv;
}

extern "C" void kernel_launch(void* const* d_in, const int* in_sizes, int n_in,
                              void* d_out, int out_size)
{
    const float* x = (const float*)d_in[0];
    float* out = (float*)d_out;
    const int total = BATCH * NANCH * HW;
    const int threads = 256;
    const int blocks = (total + threads - 1) / threads;
    region_kernel<<<blocks, threads>>>(x, out);
}